// round 4
// baseline (speedup 1.0000x reference)
#include <cuda_runtime.h>
#include <stdint.h>

#define BATCH    16
#define NBOX     4096
#define NCLS     80
#define MAX_DET  100
#define IOU_THR  0.5f
#define CONF_THR 0.5f
#define FULL     0xffffffffu
#define CHUNK    128

// scratch: per-row sort keys  (score_bits << 32) | (0xFFFFFFFF - idx)
__device__ unsigned long long g_keys[BATCH * NBOX];

// ---------------------------------------------------------------------------
// Kernel 1: softmax(square(x*10)) per row, write cls_predictions, emit keys.
// ---------------------------------------------------------------------------
__global__ void __launch_bounds__(256)
softmax_key_kernel(const float* __restrict__ cls_in,
                   float* __restrict__ cls_out,
                   unsigned long long* __restrict__ keys)
{
    const int lane = threadIdx.x & 31;
    const int row  = blockIdx.x * (blockDim.x >> 5) + (threadIdx.x >> 5);
    if (row >= BATCH * NBOX) return;

    const float* in = cls_in + (size_t)row * NCLS;

    const bool has2 = lane < (NCLS - 64);
    float x0 = in[lane]      * 10.0f;
    float x1 = in[lane + 32] * 10.0f;
    float x2 = has2 ? in[lane + 64] * 10.0f : 0.0f;
    float a0 = x0 * x0, a1 = x1 * x1, a2 = x2 * x2;

    float amax = fmaxf(a0, a1);
    if (has2) amax = fmaxf(amax, a2);
    #pragma unroll
    for (int o = 16; o; o >>= 1)
        amax = fmaxf(amax, __shfl_xor_sync(FULL, amax, o));

    float e0 = expf(a0 - amax);
    float e1 = expf(a1 - amax);
    float e2 = has2 ? expf(a2 - amax) : 0.0f;

    float s = e0 + e1 + e2;
    #pragma unroll
    for (int o = 16; o; o >>= 1)
        s += __shfl_xor_sync(FULL, s, o);

    const float recip = 1.0f / s;
    float o0 = e0 * recip, o1 = e1 * recip, o2 = e2 * recip;

    float* out = cls_out + (size_t)row * NCLS;
    out[lane]      = o0;
    out[lane + 32] = o1;
    if (has2) out[lane + 64] = o2;

    float m = fmaxf(o0, o1);
    if (has2) m = fmaxf(m, o2);
    #pragma unroll
    for (int o = 16; o; o >>= 1)
        m = fmaxf(m, __shfl_xor_sync(FULL, m, o));

    if (lane == 0) {
        const unsigned n = (unsigned)(row & (NBOX - 1));
        keys[row] = ((unsigned long long)__float_as_uint(m) << 32)
                  | (unsigned long long)(0xffffffffu - n);
    }
}

// ---------------------------------------------------------------------------
// Kernel 2: per-batch sort + block-parallel chunked NMS, all in shared memory.
// Dynamic smem: float4 sbox[NBOX] | u64 sk[NBOX] | float sarea[NBOX]
// ---------------------------------------------------------------------------
__global__ void __launch_bounds__(1024)
nms_kernel(const float* __restrict__ boxes,        // [B,N,4]
           const float* __restrict__ cls_soft,     // [B,N,C]
           const unsigned long long* __restrict__ keys,
           float* __restrict__ nms_box,            // [B,MAX_DET,4]
           float* __restrict__ nms_cls)            // [B,MAX_DET,C]
{
    extern __shared__ char dyn[];
    float4*             sbox  = (float4*)dyn;                       // 64KB
    unsigned long long* sk    = (unsigned long long*)(sbox + NBOX); // 32KB
    float*              sarea = (float*)(sk + NBOX);                // 16KB

    // kept set
    __shared__ float4 kbox[MAX_DET];            // y1,x1,y2,x2
    __shared__ float  kar[MAX_DET];
    __shared__ int    kidx[MAX_DET];
    // current chunk
    __shared__ float4        cbox[CHUNK];
    __shared__ float         car[CHUNK];
    __shared__ int           cidx[CHUNK];
    __shared__ unsigned char svalid[CHUNK];
    __shared__ unsigned char ssup[CHUNK];
    __shared__ int s_count, s_stop;

    const int b    = blockIdx.x;
    const int tid  = threadIdx.x;
    const int lane = tid & 31;
    const int warp = tid >> 5;
    const int nwarps = blockDim.x >> 5;

    // ---- load keys + pre-normalized boxes into smem ----
    const float4* bb4 = (const float4*)(boxes + (size_t)b * NBOX * 4);
    for (int i = tid; i < NBOX; i += blockDim.x) {
        sk[i] = keys[b * NBOX + i];
        float4 r = bb4[i];
        float y1 = fminf(r.x, r.z), y2 = fmaxf(r.x, r.z);
        float x1 = fminf(r.y, r.w), x2 = fmaxf(r.y, r.w);
        sbox[i]  = make_float4(y1, x1, y2, x2);
        sarea[i] = (y2 - y1) * (x2 - x1);
    }
    if (tid == 0) { s_count = 0; s_stop = 0; }
    __syncthreads();

    // ---- bitonic sort, descending ----
    // stage A: all k<=32 fused, pure warp shuffles
    for (int seg = warp; seg < NBOX / 32; seg += nwarps) {
        const int i = (seg << 5) + lane;
        unsigned long long v = sk[i];
        #pragma unroll
        for (int k = 2; k <= 32; k <<= 1) {
            const bool desc = ((i & k) == 0);
            #pragma unroll
            for (int j = k >> 1; j >= 1; j >>= 1) {
                unsigned long long w = __shfl_xor_sync(FULL, v, j);
                bool upper   = (i & j) != 0;
                bool takeMax = desc ^ upper;
                v = takeMax ? (v > w ? v : w) : (v < w ? v : w);
            }
        }
        sk[i] = v;
    }
    __syncthreads();

    // stage B: k>=64; j>=32 via smem, j<=16 via shuffles
    for (int k = 64; k <= NBOX; k <<= 1) {
        for (int j = k >> 1; j >= 32; j >>= 1) {
            for (int p = tid; p < NBOX / 2; p += blockDim.x) {
                int i = ((p & ~(j - 1)) << 1) | (p & (j - 1));
                int l = i | j;
                unsigned long long a = sk[i], c = sk[l];
                bool sw = ((i & k) == 0) ? (a < c) : (a > c);
                if (sw) { sk[i] = c; sk[l] = a; }
            }
            __syncthreads();
        }
        for (int seg = warp; seg < NBOX / 32; seg += nwarps) {
            const int i = (seg << 5) + lane;
            unsigned long long v = sk[i];
            const bool desc = ((i & k) == 0);
            #pragma unroll
            for (int j = 16; j >= 1; j >>= 1) {
                unsigned long long w = __shfl_xor_sync(FULL, v, j);
                bool upper   = (i & j) != 0;
                bool takeMax = desc ^ upper;
                v = takeMax ? (v > w ? v : w) : (v < w ? v : w);
            }
            sk[i] = v;
        }
        __syncthreads();
    }

    // ---- block-parallel chunked greedy NMS ----
    for (int r = 0; r < NBOX; r += CHUNK) {
        // phase 1: stage candidate data (threads 0..CHUNK-1)
        if (tid < CHUNK) {
            const unsigned long long key = sk[r + tid];
            const float score = __uint_as_float((unsigned)(key >> 32));
            const bool  valid = score > CONF_THR;
            const int   idx = (int)(0xffffffffu - (unsigned)(key & 0xffffffffu));
            float4 c = make_float4(0.f, 0.f, 0.f, 0.f);
            float  a = 0.f;
            if (valid) { c = sbox[idx]; a = sarea[idx]; }
            cbox[tid] = c; car[tid] = a; cidx[tid] = idx;
            svalid[tid] = valid ? 1 : 0;
        }
        __syncthreads();

        // phase 2: every candidate vs all previously-kept boxes.
        // 8 threads per candidate, fixed-trip loop (pipelined, no early exit).
        {
            const int cand = tid >> 3, sub = tid & 7;
            const float4 c  = cbox[cand];
            const float  ca = car[cand];
            const int    cnt = s_count;
            bool sup = false;
            for (int j = sub; j < cnt; j += 8) {
                float4 kb = kbox[j];
                float  ka = kar[j];
                float ih = fmaxf(0.0f, fminf(c.z, kb.z) - fmaxf(c.x, kb.x));
                float iw = fmaxf(0.0f, fminf(c.w, kb.w) - fmaxf(c.y, kb.y));
                float inter = ih * iw;
                float uni   = ca + ka - inter;
                float iou   = (inter > 0.0f) ? inter / uni : 0.0f;
                sup |= (iou > IOU_THR);
            }
            unsigned bal = __ballot_sync(FULL, sup);
            if (sub == 0)
                ssup[cand] = ((bal >> (lane & 24)) & 0xFFu) ? 1 : 0;
        }
        __syncthreads();

        // phase 3: warp 0 resolves intra-chunk order (serial only per keep)
        if (warp == 0) {
            float4 rb[4]; float ra[4]; int ridx[4];
            bool ralive[4], rvalid[4];
            #pragma unroll
            for (int s = 0; s < 4; s++) {
                const int sl = (s << 5) + lane;
                rb[s]     = cbox[sl];
                ra[s]     = car[sl];
                ridx[s]   = cidx[sl];
                rvalid[s] = svalid[sl] != 0;
                ralive[s] = rvalid[s] && (ssup[sl] == 0);
            }
            unsigned m0 = __ballot_sync(FULL, ralive[0]);
            unsigned m1 = __ballot_sync(FULL, ralive[1]);
            unsigned m2 = __ballot_sync(FULL, ralive[2]);
            unsigned m3 = __ballot_sync(FULL, ralive[3]);
            unsigned v0 = __ballot_sync(FULL, rvalid[0]);
            unsigned v1 = __ballot_sync(FULL, rvalid[1]);
            unsigned v2 = __ballot_sync(FULL, rvalid[2]);
            unsigned v3 = __ballot_sync(FULL, rvalid[3]);
            const bool any_invalid = (v0 & v1 & v2 & v3) != FULL;

            int count = s_count;
            while (count < MAX_DET) {
                int grp, i;
                if      (m0) { grp = 0; i = __ffs(m0) - 1; }
                else if (m1) { grp = 1; i = __ffs(m1) - 1; }
                else if (m2) { grp = 2; i = __ffs(m2) - 1; }
                else if (m3) { grp = 3; i = __ffs(m3) - 1; }
                else break;
                const int slot = (grp << 5) + i;

                const float y1 = __shfl_sync(FULL, rb[grp].x, i);
                const float x1 = __shfl_sync(FULL, rb[grp].y, i);
                const float y2 = __shfl_sync(FULL, rb[grp].z, i);
                const float x2 = __shfl_sync(FULL, rb[grp].w, i);
                const float a  = __shfl_sync(FULL, ra[grp],   i);
                const int   ki = __shfl_sync(FULL, ridx[grp], i);
                if (lane == 0) {
                    kbox[count] = make_float4(y1, x1, y2, x2);
                    kar[count]  = a;
                    kidx[count] = ki;
                }
                count++;
                if (lane == i) ralive[grp] = false;

                #pragma unroll
                for (int s = 0; s < 4; s++) {
                    if (ralive[s] && ((s << 5) + lane) > slot) {
                        float ih = fmaxf(0.0f, fminf(rb[s].z, y2) - fmaxf(rb[s].x, y1));
                        float iw = fmaxf(0.0f, fminf(rb[s].w, x2) - fmaxf(rb[s].y, x1));
                        float inter = ih * iw;
                        float uni   = ra[s] + a - inter;
                        float iou   = (inter > 0.0f) ? inter / uni : 0.0f;
                        if (iou > IOU_THR) ralive[s] = false;
                    }
                }
                m0 = __ballot_sync(FULL, ralive[0]);
                m1 = __ballot_sync(FULL, ralive[1]);
                m2 = __ballot_sync(FULL, ralive[2]);
                m3 = __ballot_sync(FULL, ralive[3]);
            }
            if (lane == 0) {
                s_count = count;
                s_stop  = (count >= MAX_DET) || any_invalid;
            }
        }
        __syncthreads();
        if (s_stop) break;
    }

    const int count = s_count;

    // ---- outputs (zero-pad beyond count) ----
    float* ob = nms_box + (size_t)b * MAX_DET * 4;
    for (int t = tid; t < MAX_DET * 4; t += blockDim.x) {
        int k = t >> 2, c = t & 3;
        ob[t] = (k < count)
              ? boxes[(size_t)b * NBOX * 4 + (size_t)kidx[k] * 4 + c]
              : 0.0f;
    }
    float* oc = nms_cls + (size_t)b * MAX_DET * NCLS;
    for (int t = tid; t < MAX_DET * NCLS; t += blockDim.x) {
        int k = t / NCLS, c = t % NCLS;
        oc[t] = (k < count)
              ? cls_soft[((size_t)b * NBOX + (size_t)kidx[k]) * NCLS + c]
              : 0.0f;
    }
}

// ---------------------------------------------------------------------------
extern "C" void kernel_launch(void* const* d_in, const int* in_sizes, int n_in,
                              void* d_out, int out_size)
{
    const float* boxes;
    const float* cls;
    if (in_sizes[0] == BATCH * NBOX * 4) {
        boxes = (const float*)d_in[0];
        cls   = (const float*)d_in[1];
    } else {
        boxes = (const float*)d_in[1];
        cls   = (const float*)d_in[0];
    }

    float* out      = (float*)d_out;
    float* nms_box  = out;                                  // [16,100,4]
    float* nms_cls  = out + BATCH * MAX_DET * 4;            // [16,100,80]
    float* cls_pred = out + BATCH * MAX_DET * 4
                          + BATCH * MAX_DET * NCLS;         // [16,4096,80]

    unsigned long long* keys = nullptr;
    cudaGetSymbolAddress((void**)&keys, g_keys);

    const int DYN_SMEM = NBOX * (int)sizeof(float4)
                       + NBOX * (int)sizeof(unsigned long long)
                       + NBOX * (int)sizeof(float);         // 112 KB
    static int smem_set = 0;
    if (!smem_set) {
        cudaFuncSetAttribute(nms_kernel,
                             cudaFuncAttributeMaxDynamicSharedMemorySize,
                             DYN_SMEM);
        smem_set = 1;
    }

    const int rows = BATCH * NBOX;
    softmax_key_kernel<<<rows / 8, 256>>>(cls, cls_pred, keys);
    nms_kernel<<<BATCH, 1024, DYN_SMEM>>>(boxes, cls_pred, keys, nms_box, nms_cls);
}